// round 6
// baseline (speedup 1.0000x reference)
#include <cuda_runtime.h>
#include <cuda_fp16.h>
#include <cstdint>
#include <math.h>

#define MM 16384          // B*L
#define KW 16             // window

// ---------------------------------------------------------------------------
// Device scratch (allocation-free rule: device globals)
// ---------------------------------------------------------------------------
__device__ __half g_xhi[(size_t)MM * 256];
__device__ __half g_xlo[(size_t)MM * 256];
__device__ __half g_Hhi[2][(size_t)MM * 256];
__device__ __half g_Hlo[2][(size_t)MM * 256];
__device__ float  g_Gx[(size_t)MM * 768];          // x@W_ih^T + b_ih, gate-major per ct
// Packed weights: [ct][kc][row96][k64], row = sub*48 + gate*16 + c16
__device__ __half g_Wih_p[8 * 4 * 96 * 64];
__device__ __half g_Whh_p[8 * 4 * 96 * 64];

#define SWZ(o) ((o) ^ (((o) >> 3) & 0x70))

// SMEM (112 KB total, 2 CTA/SM):
//   B   : 4 chunks x 96 rows x 128B = 48 KB  (resident, whole K)
//   A-hi: 4 chunks x 64 rows x 128B = 32 KB  (resident, whole K)
//   A-lo: 32 KB
#define OFF_B  0
#define OFF_AH 49152
#define OFF_AL 81920
#define SMEM_BYTES 114688

// ---------------------------------------------------------------------------
// PTX helpers
// ---------------------------------------------------------------------------
__device__ __forceinline__ uint32_t smem_u32(const void* p) {
    uint32_t a;
    asm("{ .reg .u64 t; cvta.to.shared.u64 t, %1; cvt.u32.u64 %0, t; }"
        : "=r"(a) : "l"(p));
    return a;
}
__device__ __forceinline__ void cp16(uint32_t d, const void* s) {
    asm volatile("cp.async.cg.shared.global [%0], [%1], 16;"
                 :: "r"(d), "l"(s) : "memory");
}
__device__ __forceinline__ void cp_commit() { asm volatile("cp.async.commit_group;" ::: "memory"); }
__device__ __forceinline__ void cp_wait0()  { asm volatile("cp.async.wait_group 0;" ::: "memory"); }

__device__ __forceinline__ void ldm4(uint32_t a, uint32_t* r) {
    asm volatile("ldmatrix.sync.aligned.m8n8.x4.shared.b16 {%0,%1,%2,%3}, [%4];"
                 : "=r"(r[0]), "=r"(r[1]), "=r"(r[2]), "=r"(r[3]) : "r"(a));
}
__device__ __forceinline__ void mma16816(float* c, const uint32_t* a, const uint32_t* b) {
    asm volatile("mma.sync.aligned.m16n8k16.row.col.f32.f16.f16.f32 "
                 "{%0,%1,%2,%3}, {%4,%5,%6,%7}, {%8,%9}, {%0,%1,%2,%3};"
                 : "+f"(c[0]), "+f"(c[1]), "+f"(c[2]), "+f"(c[3])
                 : "r"(a[0]), "r"(a[1]), "r"(a[2]), "r"(a[3]), "r"(b[0]), "r"(b[1]));
}
__device__ __forceinline__ float sigm(float x) {
    return 1.f / (1.f + __expf(-x));
}
__device__ __forceinline__ float ftanh(float x) {
    return 1.f - 2.f / (__expf(2.f * x) + 1.f);
}

// ---------------------------------------------------------------------------
// Prep kernels
// ---------------------------------------------------------------------------
__global__ void pack_x_kernel(const float* __restrict__ x) {
    size_t i = (size_t)blockIdx.x * 256 + threadIdx.x;
    float f = x[i];
    __half h = __float2half(f);
    g_xhi[i] = h;
    g_xlo[i] = __float2half(f - __half2float(h));
}

// row = sub*48 + g*16 + c  ->  W row = g*256 + ct*32 + sub*16 + c
__global__ void pack_w_kernel(const float* __restrict__ W_ih,
                              const float* __restrict__ W_hh) {
    int idx = blockIdx.x * 256 + threadIdx.x;        // < 196608
    int k   = idx & 63;
    int r2  = idx >> 6;
    int row = r2 % 96;
    int r3  = r2 / 96;
    int kc  = r3 & 3;
    int ct  = r3 >> 2;
    int sub = row / 48;
    int rem = row % 48;
    int g = rem >> 4, c = rem & 15;
    int widx = (g * 256 + ct * 32 + sub * 16 + c) * 256 + kc * 64 + k;
    g_Wih_p[idx] = __float2half(W_ih[widx]);
    g_Whh_p[idx] = __float2half(W_hh[widx]);
}

// ---------------------------------------------------------------------------
// Step 0 (h = 0): pure elementwise
// ---------------------------------------------------------------------------
__global__ void step0_kernel(const float* __restrict__ b_ih,
                             const float* __restrict__ b_hh) {
    int idx = blockIdx.x * 256 + threadIdx.x;
    int m = idx >> 8, col = idx & 255;
    int ct = col >> 5, c = col & 31;
    int l = m & 1023;
    float gir, giz, gin;
    if (l - (KW - 1) >= 0) {
        const float* gx = &g_Gx[(size_t)(m - (KW - 1)) * 768 + ct * 96];
        gir = gx[c]; giz = gx[32 + c]; gin = gx[64 + c];
    } else {
        gir = b_ih[col];
        giz = b_ih[256 + col];
        gin = b_ih[512 + col];
    }
    float r = sigm(gir + b_hh[col]);
    float z = sigm(giz + b_hh[256 + col]);
    float n = ftanh(fmaf(r, b_hh[512 + col], gin));
    float h = (1.f - z) * n;
    __half hh = __float2half(h);
    g_Hhi[0][idx] = hh;
    g_Hlo[0][idx] = __float2half(h - __half2float(hh));
}

// ---------------------------------------------------------------------------
// Fused GEMM (mma.sync fp16 -> fp32) + epilogue — single-shot operand load.
//   mode 0: Gx = x @ W_ih^T + b_ih        (lo corrects all gates)
//   mode 1: gh = h @ W_hh^T + GRU update  (lo corrects n-gate only)
// CTA 64M x 96N; 8 warps = 4 M-groups(16) x 2 N-subs(48 = 16 h-cols x 3 gates).
// ALL operands (B 48KB + A-hi 32KB + A-lo 32KB) loaded in ONE cp.async volley,
// ONE wait, ONE __syncthreads, then 16 unobstructed k-steps of LDSM+HMMA.
// ---------------------------------------------------------------------------
__global__ void __launch_bounds__(256, 2)
gemm_fused(int mode, int t, int src, int dst,
           const float* __restrict__ b_ih, const float* __restrict__ b_hh,
           float* __restrict__ fout)
{
    extern __shared__ char smem[];
    const int tid = threadIdx.x, wid = tid >> 5, lane = tid & 31;
    const int mg  = wid & 3;           // M group (16 rows)
    const int sub = wid >> 2;          // N sub (16 h-cols x 3 gates)
    const int ct  = blockIdx.x;
    const int m0  = blockIdx.y * 64;
    const uint32_t sb = smem_u32(smem);

    const __half* __restrict__ Ahi = (mode == 0) ? g_xhi : g_Hhi[src];
    const __half* __restrict__ Alo = (mode == 0) ? g_xlo : g_Hlo[src];
    const __half* __restrict__ B   = (mode == 0) ? g_Wih_p : g_Whh_p;
    const bool lo_all = (mode == 0);

    float acc[6][4];
    #pragma unroll
    for (int p = 0; p < 6; p++)
        #pragma unroll
        for (int j = 0; j < 4; j++) acc[p][j] = 0.f;

    // ---- single-shot load: B (12/thread) + A hi/lo (16/thread) ----
    {
        const __half* Bbase = B + (size_t)ct * 4 * 96 * 64;
        #pragma unroll
        for (int r = 0; r < 12; r++) {
            int idx = tid + 256 * r;             // < 3072
            int kc = idx / 768;
            int e  = idx - kc * 768;
            int row = e >> 3, u = e & 7;
            cp16(sb + OFF_B + kc * 12288 + SWZ(row * 128 + u * 16),
                 Bbase + (size_t)(kc * 96 + row) * 64 + u * 8);
        }
        #pragma unroll
        for (int r = 0; r < 8; r++) {
            int idx = tid + 256 * r;             // < 2048 = 4 kc x 64 rows x 8 u
            int kc  = idx >> 9;
            int e   = idx & 511;
            int row = e >> 3, u = e & 7;
            size_t off = (size_t)(m0 + row) * 256 + kc * 64 + u * 8;
            uint32_t d = kc * 8192 + SWZ(row * 128 + u * 16);
            cp16(sb + OFF_AH + d, Ahi + off);
            cp16(sb + OFF_AL + d, Alo + off);
        }
        cp_commit();
    }
    cp_wait0();
    __syncthreads();        // the ONLY barrier before the epilogue

    // ---- 16 k-steps, no syncs ----
    #pragma unroll
    for (int kc = 0; kc < 4; kc++) {
        uint32_t abufh = sb + OFF_AH + kc * 8192;
        uint32_t abufl = sb + OFF_AL + kc * 8192;
        uint32_t bbuf  = sb + OFF_B  + kc * 12288;
        #pragma unroll
        for (int ks = 0; ks < 4; ks++) {
            uint32_t af[4], al[4];
            {
                int row = mg * 16 + (lane & 15);
                int colb = ks * 32 + ((lane >> 4) << 4);
                uint32_t d = SWZ(row * 128 + colb);
                ldm4(abufh + d, af);
                ldm4(abufl + d, al);
            }
            #pragma unroll
            for (int q = 0; q < 3; q++) {        // gate: 0=r,1=z,2=n
                uint32_t bf[4];
                int n = sub * 48 + q * 16 + (lane & 7) + ((lane >> 4) << 3);
                int colb = ks * 32 + (((lane >> 3) & 1) << 4);
                ldm4(bbuf + SWZ(n * 128 + colb), bf);
                mma16816(acc[2 * q + 0], af, bf + 0);
                mma16816(acc[2 * q + 1], af, bf + 2);
                if (lo_all || q == 2) {
                    mma16816(acc[2 * q + 0], al, bf + 0);
                    mma16816(acc[2 * q + 1], al, bf + 2);
                }
            }
        }
    }

    // ---------------- epilogue (registers only) ----------------
    const int gid = lane >> 2, tid2 = lane & 3;

    if (mode == 0) {
        #pragma unroll
        for (int i = 0; i < 2; i++) {
            int m = m0 + mg * 16 + gid + i * 8;
            #pragma unroll
            for (int q = 0; q < 3; q++) {
                #pragma unroll
                for (int cb = 0; cb < 2; cb++) {
                    #pragma unroll
                    for (int j = 0; j < 2; j++) {
                        int c = sub * 16 + cb * 8 + tid2 * 2 + j;   // 0..31
                        g_Gx[(size_t)m * 768 + ct * 96 + q * 32 + c] =
                            acc[2 * q + cb][i * 2 + j] +
                            b_ih[q * 256 + ct * 32 + c];
                    }
                }
            }
        }
    } else {
        __half* __restrict__ Hdh = g_Hhi[dst];
        __half* __restrict__ Hdl = g_Hlo[dst];
        #pragma unroll
        for (int i = 0; i < 2; i++) {
            int m = m0 + mg * 16 + gid + i * 8;
            int l = m & 1023;
            bool valid = (l - (KW - 1) + t) >= 0;
            const float* gx = &g_Gx[(size_t)(m - (KW - 1) + t) * 768 + ct * 96];
            #pragma unroll
            for (int cb = 0; cb < 2; cb++) {
                #pragma unroll
                for (int j = 0; j < 2; j++) {
                    int c = sub * 16 + cb * 8 + tid2 * 2 + j;   // 0..31
                    int col = ct * 32 + c;
                    float gir, giz, gin;
                    if (valid) { gir = gx[c]; giz = gx[32 + c]; gin = gx[64 + c]; }
                    else {
                        gir = b_ih[col];
                        giz = b_ih[256 + col];
                        gin = b_ih[512 + col];
                    }
                    float rr = sigm(gir + acc[0 + cb][i * 2 + j] + b_hh[col]);
                    float zz = sigm(giz + acc[2 + cb][i * 2 + j] + b_hh[256 + col]);
                    float nn = ftanh(fmaf(rr, acc[4 + cb][i * 2 + j] +
                                              b_hh[512 + col], gin));
                    size_t ga = (size_t)m * 256 + col;
                    float hp = __half2float(Ahi[ga]) + __half2float(Alo[ga]);
                    float h = fmaf(zz, hp - nn, nn);    // (1-z)*n + z*hprev
                    if (t == KW - 1) {
                        fout[ga] = h;
                    } else {
                        __half hh = __float2half(h);
                        Hdh[ga] = hh;
                        Hdl[ga] = __float2half(h - __half2float(hh));
                    }
                }
            }
        }
    }
}

// ---------------------------------------------------------------------------
extern "C" void kernel_launch(void* const* d_in, const int* in_sizes, int n_in,
                              void* d_out, int out_size)
{
    const float* x    = (const float*)d_in[0];
    const float* W_ih = (const float*)d_in[1];
    const float* W_hh = (const float*)d_in[2];
    const float* b_ih = (const float*)d_in[3];
    const float* b_hh = (const float*)d_in[4];
    float* out = (float*)d_out;

    cudaFuncSetAttribute(gemm_fused,
                         cudaFuncAttributeMaxDynamicSharedMemorySize, SMEM_BYTES);

    pack_x_kernel<<<MM * 256 / 256, 256>>>(x);
    pack_w_kernel<<<8 * 4 * 96 * 64 / 256, 256>>>(W_ih, W_hh);

    // Gx = x @ W_ih^T + b_ih
    gemm_fused<<<dim3(8, MM / 64), 256, SMEM_BYTES>>>(
        0, 0, 0, 0, b_ih, b_hh, nullptr);

    // step 0 (h = 0): elementwise
    step0_kernel<<<MM, 256>>>(b_ih, b_hh);

    // steps 1..15: fused GEMM + GRU update; last writes d_out
    for (int t = 1; t < KW; t++) {
        gemm_fused<<<dim3(8, MM / 64), 256, SMEM_BYTES>>>(
            1, t, (t - 1) & 1, t & 1, b_ih, b_hh, (t == KW - 1) ? out : nullptr);
    }
}

// round 7
// speedup vs baseline: 1.3302x; 1.3302x over previous
#include <cuda_runtime.h>
#include <cuda_fp16.h>
#include <cstdint>
#include <math.h>

#define MM 16384          // B*L
#define KW 16             // window

// ---------------------------------------------------------------------------
// Device scratch (allocation-free rule: device globals)
// ---------------------------------------------------------------------------
__device__ __half g_xhi[(size_t)MM * 256];
__device__ __half g_xlo[(size_t)MM * 256];
__device__ float  g_Gx[(size_t)MM * 768];        // x@W_ih^T + b_ih, [m][ct*96 + q*32 + c]
__device__ __half g_Wih_p[8 * 4 * 96 * 64];      // W_ih for Gx GEMM (R5 ldmatrix layout)
__device__ uint4  g_Wfrag[8 * 16 * 6 * 32];      // W_hh in mma B-fragment order

#define SWZ(o) ((o) ^ (((o) >> 3) & 0x70))

// Gx GEMM smem (R5 layout)
#define GX_OFF_B 0
#define GX_OFF_A 49152
#define GX_SMEM  114688

// fused kernel smem: H double buffer [buf][kc][row112][128B] + biases
#define FK_CHUNK 14336           // 112 rows * 128 B
#define FK_BUF   57344           // 4 chunks
#define FK_BIAS  114688
#define FK_SMEM  (114688 + 6144)

// ---------------------------------------------------------------------------
// PTX helpers
// ---------------------------------------------------------------------------
__device__ __forceinline__ uint32_t smem_u32(const void* p) {
    uint32_t a;
    asm("{ .reg .u64 t; cvta.to.shared.u64 t, %1; cvt.u32.u64 %0, t; }"
        : "=r"(a) : "l"(p));
    return a;
}
__device__ __forceinline__ void cp16(uint32_t d, const void* s) {
    asm volatile("cp.async.cg.shared.global [%0], [%1], 16;"
                 :: "r"(d), "l"(s) : "memory");
}
__device__ __forceinline__ void cp_commit() { asm volatile("cp.async.commit_group;" ::: "memory"); }
__device__ __forceinline__ void cp_wait1()  { asm volatile("cp.async.wait_group 1;" ::: "memory"); }
__device__ __forceinline__ void cp_wait0()  { asm volatile("cp.async.wait_group 0;" ::: "memory"); }

__device__ __forceinline__ void ldm4(uint32_t a, uint32_t* r) {
    asm volatile("ldmatrix.sync.aligned.m8n8.x4.shared.b16 {%0,%1,%2,%3}, [%4];"
                 : "=r"(r[0]), "=r"(r[1]), "=r"(r[2]), "=r"(r[3]) : "r"(a));
}
__device__ __forceinline__ void mma16816(float* c, const uint32_t* a, const uint32_t* b) {
    asm volatile("mma.sync.aligned.m16n8k16.row.col.f32.f16.f16.f32 "
                 "{%0,%1,%2,%3}, {%4,%5,%6,%7}, {%8,%9}, {%0,%1,%2,%3};"
                 : "+f"(c[0]), "+f"(c[1]), "+f"(c[2]), "+f"(c[3])
                 : "r"(a[0]), "r"(a[1]), "r"(a[2]), "r"(a[3]), "r"(b[0]), "r"(b[1]));
}
__device__ __forceinline__ float sigm(float x)  { return 1.f / (1.f + __expf(-x)); }
__device__ __forceinline__ float ftanh(float x) { return 1.f - 2.f / (__expf(2.f * x) + 1.f); }

// ---------------------------------------------------------------------------
// Prep kernels
// ---------------------------------------------------------------------------
__global__ void pack_x_kernel(const float* __restrict__ x) {
    size_t i = (size_t)blockIdx.x * 256 + threadIdx.x;
    float f = x[i];
    __half h = __float2half(f);
    g_xhi[i] = h;
    g_xlo[i] = __float2half(f - __half2float(h));
}

// W_ih in R5 ldmatrix layout: [ct][kc][row96][k64], row = sub*48 + g*16 + c
__global__ void pack_wih_kernel(const float* __restrict__ W_ih) {
    int idx = blockIdx.x * 256 + threadIdx.x;    // < 196608
    int k   = idx & 63;
    int r2  = idx >> 6;
    int row = r2 % 96;
    int r3  = r2 / 96;
    int kc  = r3 & 3;
    int ct  = r3 >> 2;
    int sub = row / 48;
    int rem = row % 48;
    int g = rem >> 4, c = rem & 15;
    g_Wih_p[idx] = __float2half(
        W_ih[(size_t)(g * 256 + ct * 32 + sub * 16 + c) * 256 + kc * 64 + k]);
}

// W_hh in mma.m16n8k16 B-fragment order:
//   g_Wfrag[((ct*16 + ks16)*6 + p)*32 + lane] = 16B holding blocks nb=2p,2p+1
//   block nb -> gate q = nb>>2, col c = (nb&3)*8 + (lane>>2)
//   reg r: nb = p*2 + (r>>1), k = ks16*16 + (r&1)*8 + (lane&3)*2 + {0,1}
__global__ void pack_wfrag_kernel(const float* __restrict__ W_hh) {
    int idx = blockIdx.x * 256 + threadIdx.x;    // < 24576
    int lane = idx & 31;
    int r2 = idx >> 5;
    int p  = r2 % 6;
    int r3 = r2 / 6;
    int ks = r3 & 15;
    int ct = r3 >> 4;
    uint32_t u[4];
    #pragma unroll
    for (int r = 0; r < 4; r++) {
        int nb = p * 2 + (r >> 1);
        int q  = nb >> 2;
        int cc = (nb & 3) * 8 + (lane >> 2);
        int row = q * 256 + ct * 32 + cc;
        int k0  = ks * 16 + (r & 1) * 8 + (lane & 3) * 2;
        __half h0 = __float2half(W_hh[(size_t)row * 256 + k0]);
        __half h1 = __float2half(W_hh[(size_t)row * 256 + k0 + 1]);
        u[r] = (uint32_t)__half_as_ushort(h0) |
               ((uint32_t)__half_as_ushort(h1) << 16);
    }
    g_Wfrag[idx] = make_uint4(u[0], u[1], u[2], u[3]);
}

// ---------------------------------------------------------------------------
// Gx GEMM: Gx = x @ W_ih^T + b_ih  (R5 structure, mode 0, lo-correct all gates)
// CTA 128M x 96N; 8 warps = 4 Mg(32) x 2 sub(48N); B resident, A pipelined.
// ---------------------------------------------------------------------------
__global__ void __launch_bounds__(256, 2)
gx_gemm(const float* __restrict__ b_ih)
{
    extern __shared__ char smem[];
    const int tid = threadIdx.x, wid = tid >> 5, lane = tid & 31;
    const int mg  = wid & 3;
    const int sub = wid >> 2;
    const int ct  = blockIdx.x;
    const int m0  = blockIdx.y * 128;
    const uint32_t sb = smem_u32(smem);

    float acc[2][6][4];
    #pragma unroll
    for (int mi = 0; mi < 2; mi++)
        #pragma unroll
        for (int p = 0; p < 6; p++)
            #pragma unroll
            for (int j = 0; j < 4; j++) acc[mi][p][j] = 0.f;

    {
        const __half* Bbase = g_Wih_p + (size_t)ct * 4 * 96 * 64;
        #pragma unroll
        for (int r = 0; r < 12; r++) {
            int idx = tid + 256 * r;
            int kc = idx / 768;
            int e  = idx - kc * 768;
            int row = e >> 3, u = e & 7;
            cp16(sb + GX_OFF_B + kc * 12288 + SWZ(row * 128 + u * 16),
                 Bbase + (size_t)(kc * 96 + row) * 64 + u * 8);
        }
    }
    auto load_A = [&](int kc, int buf) {
        uint32_t base = sb + GX_OFF_A + buf * 32768;
        #pragma unroll
        for (int r = 0; r < 4; r++) {
            int idx = tid + 256 * r;
            int row = idx >> 3, u = idx & 7;
            size_t off = (size_t)(m0 + row) * 256 + kc * 64 + u * 8;
            uint32_t d = SWZ(row * 128 + u * 16);
            cp16(base + d, g_xhi + off);
            cp16(base + 16384 + d, g_xlo + off);
        }
        cp_commit();
    };

    load_A(0, 0);
    #pragma unroll 1
    for (int kc = 0; kc < 4; kc++) {
        if (kc + 1 < 4) { load_A(kc + 1, (kc + 1) & 1); cp_wait1(); }
        else            { cp_wait0(); }
        __syncthreads();

        uint32_t abufh = sb + GX_OFF_A + (kc & 1) * 32768;
        uint32_t abufl = abufh + 16384;
        uint32_t bbuf  = sb + GX_OFF_B + kc * 12288;

        #pragma unroll
        for (int ks = 0; ks < 4; ks++) {
            uint32_t af[2][4], al[2][4];
            #pragma unroll
            for (int mi = 0; mi < 2; mi++) {
                int row = mg * 32 + mi * 16 + (lane & 15);
                int colb = ks * 32 + ((lane >> 4) << 4);
                uint32_t d = SWZ(row * 128 + colb);
                ldm4(abufh + d, af[mi]);
                ldm4(abufl + d, al[mi]);
            }
            #pragma unroll
            for (int q = 0; q < 3; q++) {
                uint32_t bf[4];
                int n = sub * 48 + q * 16 + (lane & 7) + ((lane >> 4) << 3);
                int colb = ks * 32 + (((lane >> 3) & 1) << 4);
                ldm4(bbuf + SWZ(n * 128 + colb), bf);
                #pragma unroll
                for (int mi = 0; mi < 2; mi++) {
                    mma16816(acc[mi][2 * q + 0], af[mi], bf + 0);
                    mma16816(acc[mi][2 * q + 1], af[mi], bf + 2);
                    mma16816(acc[mi][2 * q + 0], al[mi], bf + 0);
                    mma16816(acc[mi][2 * q + 1], al[mi], bf + 2);
                }
            }
        }
        __syncthreads();
    }

    const int gid = lane >> 2, tid2 = lane & 3;
    #pragma unroll
    for (int mi = 0; mi < 2; mi++) {
        #pragma unroll
        for (int i = 0; i < 2; i++) {
            int m = m0 + mg * 32 + mi * 16 + gid + i * 8;
            #pragma unroll
            for (int q = 0; q < 3; q++) {
                #pragma unroll
                for (int cb = 0; cb < 2; cb++) {
                    #pragma unroll
                    for (int j = 0; j < 2; j++) {
                        int c = sub * 16 + cb * 8 + tid2 * 2 + j;   // 0..31
                        g_Gx[(size_t)m * 768 + ct * 96 + q * 32 + c] =
                            acc[mi][2 * q + cb][i * 2 + j] +
                            b_ih[q * 256 + ct * 32 + c];
                    }
                }
            }
        }
    }
}

// ---------------------------------------------------------------------------
// Fused 16-step recurrence: one kernel, H in SMEM, warp-private rows,
// W via fragment-order LDG, no CTA barriers in the t-loop.
// Grid 147 CTAs x 224 threads; CTA owns 112 M-rows; warp owns 16 rows x 96N/ct.
// ---------------------------------------------------------------------------
__global__ void __launch_bounds__(224, 1)
fused_rnn(const float* __restrict__ b_ih, const float* __restrict__ b_hh,
          float* __restrict__ fout)
{
    extern __shared__ char smem[];
    const int tid = threadIdx.x, wid = tid >> 5, lane = tid & 31;
    const int m0 = blockIdx.x * 112;
    const int mrow0 = wid * 16;
    const uint32_t sb = smem_u32(smem);
    const int gid = lane >> 2, tid2 = lane & 3;

    // stage biases once
    float* sbias = (float*)(smem + FK_BIAS);
    for (int i = tid; i < 1536; i += 224)
        sbias[i] = (i < 768) ? b_ih[i] : b_hh[i - 768];
    __syncthreads();
    const float* sbi = sbias;
    const float* sbh = sbias + 768;

    #pragma unroll 1
    for (int t = 0; t < KW; t++) {
        const uint32_t curb = sb + ((t + 1) & 1) * FK_BUF;
        const uint32_t nxtb = sb + (t & 1) * FK_BUF;
        #pragma unroll 1
        for (int ct = 0; ct < 8; ct++) {
            float acc[12][4];
            #pragma unroll
            for (int nb = 0; nb < 12; nb++)
                #pragma unroll
                for (int j2 = 0; j2 < 4; j2++) acc[nb][j2] = 0.f;

            if (t > 0) {
                const uint4* __restrict__ wp =
                    &g_Wfrag[(size_t)ct * 16 * 6 * 32 + lane];
                #pragma unroll
                for (int ks16 = 0; ks16 < 16; ks16++) {
                    uint32_t af[4];
                    {
                        int kc = ks16 >> 2, ks = ks16 & 3;
                        int row = mrow0 + (lane & 15);
                        int colb = ks * 32 + ((lane >> 4) << 4);
                        ldm4(curb + kc * FK_CHUNK + SWZ(row * 128 + colb), af);
                    }
                    #pragma unroll
                    for (int p = 0; p < 6; p++) {
                        uint4 bv = wp[(ks16 * 6 + p) * 32];
                        uint32_t bf0[2] = {bv.x, bv.y};
                        uint32_t bf1[2] = {bv.z, bv.w};
                        mma16816(acc[2 * p + 0], af, bf0);
                        mma16816(acc[2 * p + 1], af, bf1);
                    }
                }
            }

            // ---- epilogue: GRU gates, write h_next (fp16) to SMEM / out ----
            #pragma unroll
            for (int i = 0; i < 2; i++) {
                int rowl = mrow0 + gid + i * 8;          // 0..111
                int m = m0 + rowl;
                bool mval = m < MM;
                int l = m & 1023;
                bool valid = mval && (l - (KW - 1) + t >= 0);
                const float* gx = &g_Gx[(size_t)(m - (KW - 1) + t) * 768 + ct * 96];
                #pragma unroll
                for (int cb = 0; cb < 4; cb++) {
                    int c = cb * 8 + tid2 * 2;           // even, 0..30
                    int col = ct * 32 + c;
                    float2 gr, gz, gn;
                    if (valid) {
                        gr = *(const float2*)&gx[c];
                        gz = *(const float2*)&gx[32 + c];
                        gn = *(const float2*)&gx[64 + c];
                    } else {
                        gr = *(const float2*)&sbi[col];
                        gz = *(const float2*)&sbi[256 + col];
                        gn = *(const float2*)&sbi[512 + col];
                    }
                    float2 br = *(const float2*)&sbh[col];
                    float2 bz = *(const float2*)&sbh[256 + col];
                    float2 bn = *(const float2*)&sbh[512 + col];
                    float hp0 = 0.f, hp1 = 0.f;
                    if (t > 0) {
                        int kc2 = col >> 6, ch = col & 63;
                        uint32_t hv;
                        asm volatile("ld.shared.b32 %0, [%1];" : "=r"(hv)
                            : "r"(curb + kc2 * FK_CHUNK + SWZ(rowl * 128 + ch * 2)));
                        __half2 h2 = *(__half2*)&hv;
                        hp0 = __half2float(__low2half(h2));
                        hp1 = __half2float(__high2half(h2));
                    }
                    float r0 = sigm(gr.x + acc[cb][i * 2 + 0] + br.x);
                    float r1 = sigm(gr.y + acc[cb][i * 2 + 1] + br.y);
                    float z0 = sigm(gz.x + acc[4 + cb][i * 2 + 0] + bz.x);
                    float z1 = sigm(gz.y + acc[4 + cb][i * 2 + 1] + bz.y);
                    float n0 = ftanh(fmaf(r0, acc[8 + cb][i * 2 + 0] + bn.x, gn.x));
                    float n1 = ftanh(fmaf(r1, acc[8 + cb][i * 2 + 1] + bn.y, gn.y));
                    float h0 = fmaf(z0, hp0 - n0, n0);   // (1-z)n + z*hprev
                    float h1 = fmaf(z1, hp1 - n1, n1);
                    if (t == KW - 1) {
                        if (mval) {
                            float2 o = make_float2(h0, h1);
                            *(float2*)&fout[(size_t)m * 256 + col] = o;
                        }
                    } else {
                        __half2 h2 = __floats2half2_rn(h0, h1);
                        int kc2 = col >> 6, ch = col & 63;
                        uint32_t hv = *(uint32_t*)&h2;
                        asm volatile("st.shared.b32 [%0], %1;" ::
                            "r"(nxtb + kc2 * FK_CHUNK + SWZ(rowl * 128 + ch * 2)),
                            "r"(hv) : "memory");
                    }
                }
            }
        }
        __syncwarp();   // order this step's STS before next step's ldmatrix
    }
}

// ---------------------------------------------------------------------------
extern "C" void kernel_launch(void* const* d_in, const int* in_sizes, int n_in,
                              void* d_out, int out_size)
{
    const float* x    = (const float*)d_in[0];
    const float* W_ih = (const float*)d_in[1];
    const float* W_hh = (const float*)d_in[2];
    const float* b_ih = (const float*)d_in[3];
    const float* b_hh = (const float*)d_in[4];
    float* out = (float*)d_out;

    cudaFuncSetAttribute(gx_gemm,
                         cudaFuncAttributeMaxDynamicSharedMemorySize, GX_SMEM);
    cudaFuncSetAttribute(fused_rnn,
                         cudaFuncAttributeMaxDynamicSharedMemorySize, FK_SMEM);

    pack_x_kernel<<<MM * 256 / 256, 256>>>(x);
    pack_wih_kernel<<<8 * 4 * 96 * 64 / 256, 256>>>(W_ih);
    pack_wfrag_kernel<<<8 * 16 * 6 * 32 / 256, 256>>>(W_hh);

    gx_gemm<<<dim3(8, MM / 128), 256, GX_SMEM>>>(b_ih);

    fused_rnn<<<147, 224, FK_SMEM>>>(b_ih, b_hh, out);
}

// round 8
// speedup vs baseline: 2.0126x; 1.5131x over previous
#include <cuda_runtime.h>
#include <cuda_fp16.h>
#include <cstdint>
#include <math.h>

#define MM 16384          // B*L
#define KW 16             // window

// ---------------------------------------------------------------------------
// Device scratch (allocation-free rule: device globals)
// ---------------------------------------------------------------------------
__device__ __half g_xhi[(size_t)MM * 256];
__device__ __half g_xlo[(size_t)MM * 256];
__device__ float  g_Gx[(size_t)MM * 768];        // x@W_ih^T + b_ih, [m][ct*96 + q*32 + c]
__device__ __half g_Wih_p[8 * 4 * 96 * 64];      // W_ih for Gx GEMM (ldmatrix layout)
__device__ uint4  g_Wfrag[8 * 16 * 6 * 32];      // W_hh in mma B-fragment order

#define SWZ(o) ((o) ^ (((o) >> 3) & 0x70))

// Gx GEMM smem
#define GX_OFF_B 0
#define GX_OFF_A 49152
#define GX_SMEM  114688

// fused kernel smem: H double buffer [buf][kc][row112][128B] + biases
#define FK_CHUNK 14336           // 112 rows * 128 B
#define FK_BUF   57344           // 4 chunks
#define FK_BIAS  114688
#define FK_SMEM  (114688 + 6144)

// ---------------------------------------------------------------------------
// PTX helpers
// ---------------------------------------------------------------------------
__device__ __forceinline__ uint32_t smem_u32(const void* p) {
    uint32_t a;
    asm("{ .reg .u64 t; cvta.to.shared.u64 t, %1; cvt.u32.u64 %0, t; }"
        : "=r"(a) : "l"(p));
    return a;
}
__device__ __forceinline__ void cp16(uint32_t d, const void* s) {
    asm volatile("cp.async.cg.shared.global [%0], [%1], 16;"
                 :: "r"(d), "l"(s) : "memory");
}
__device__ __forceinline__ void cp_commit() { asm volatile("cp.async.commit_group;" ::: "memory"); }
__device__ __forceinline__ void cp_wait1()  { asm volatile("cp.async.wait_group 1;" ::: "memory"); }
__device__ __forceinline__ void cp_wait0()  { asm volatile("cp.async.wait_group 0;" ::: "memory"); }

__device__ __forceinline__ void ldm4(uint32_t a, uint32_t* r) {
    asm volatile("ldmatrix.sync.aligned.m8n8.x4.shared.b16 {%0,%1,%2,%3}, [%4];"
                 : "=r"(r[0]), "=r"(r[1]), "=r"(r[2]), "=r"(r[3]) : "r"(a));
}
__device__ __forceinline__ void mma16816(float* c, const uint32_t* a, const uint32_t* b) {
    asm volatile("mma.sync.aligned.m16n8k16.row.col.f32.f16.f16.f32 "
                 "{%0,%1,%2,%3}, {%4,%5,%6,%7}, {%8,%9}, {%0,%1,%2,%3};"
                 : "+f"(c[0]), "+f"(c[1]), "+f"(c[2]), "+f"(c[3])
                 : "r"(a[0]), "r"(a[1]), "r"(a[2]), "r"(a[3]), "r"(b[0]), "r"(b[1]));
}
__device__ __forceinline__ float sigm(float x)  { return 1.f / (1.f + __expf(-x)); }
__device__ __forceinline__ float ftanh(float x) { return 1.f - 2.f / (__expf(2.f * x) + 1.f); }

// ---------------------------------------------------------------------------
// Prep kernels
// ---------------------------------------------------------------------------
__global__ void pack_x_kernel(const float* __restrict__ x) {
    size_t i = (size_t)blockIdx.x * 256 + threadIdx.x;
    float f = x[i];
    __half h = __float2half(f);
    g_xhi[i] = h;
    g_xlo[i] = __float2half(f - __half2float(h));
}

// W_ih ldmatrix layout: [ct][kc][row96][k64], row = sub*48 + g*16 + c
__global__ void pack_wih_kernel(const float* __restrict__ W_ih) {
    int idx = blockIdx.x * 256 + threadIdx.x;    // < 196608
    int k   = idx & 63;
    int r2  = idx >> 6;
    int row = r2 % 96;
    int r3  = r2 / 96;
    int kc  = r3 & 3;
    int ct  = r3 >> 2;
    int sub = row / 48;
    int rem = row % 48;
    int g = rem >> 4, c = rem & 15;
    g_Wih_p[idx] = __float2half(
        W_ih[(size_t)(g * 256 + ct * 32 + sub * 16 + c) * 256 + kc * 64 + k]);
}

// W_hh in mma.m16n8k16 B-fragment order (see R7 comments)
__global__ void pack_wfrag_kernel(const float* __restrict__ W_hh) {
    int idx = blockIdx.x * 256 + threadIdx.x;    // < 24576
    int lane = idx & 31;
    int r2 = idx >> 5;
    int p  = r2 % 6;
    int r3 = r2 / 6;
    int ks = r3 & 15;
    int ct = r3 >> 4;
    uint32_t u[4];
    #pragma unroll
    for (int r = 0; r < 4; r++) {
        int nb = p * 2 + (r >> 1);
        int q  = nb >> 2;
        int cc = (nb & 3) * 8 + (lane >> 2);
        int row = q * 256 + ct * 32 + cc;
        int k0  = ks * 16 + (r & 1) * 8 + (lane & 3) * 2;
        __half h0 = __float2half(W_hh[(size_t)row * 256 + k0]);
        __half h1 = __float2half(W_hh[(size_t)row * 256 + k0 + 1]);
        u[r] = (uint32_t)__half_as_ushort(h0) |
               ((uint32_t)__half_as_ushort(h1) << 16);
    }
    g_Wfrag[idx] = make_uint4(u[0], u[1], u[2], u[3]);
}

// ---------------------------------------------------------------------------
// Gx GEMM: Gx = x @ W_ih^T + b_ih  (unchanged from R7)
// ---------------------------------------------------------------------------
__global__ void __launch_bounds__(256, 2)
gx_gemm(const float* __restrict__ b_ih)
{
    extern __shared__ char smem[];
    const int tid = threadIdx.x, wid = tid >> 5, lane = tid & 31;
    const int mg  = wid & 3;
    const int sub = wid >> 2;
    const int ct  = blockIdx.x;
    const int m0  = blockIdx.y * 128;
    const uint32_t sb = smem_u32(smem);

    float acc[2][6][4];
    #pragma unroll
    for (int mi = 0; mi < 2; mi++)
        #pragma unroll
        for (int p = 0; p < 6; p++)
            #pragma unroll
            for (int j = 0; j < 4; j++) acc[mi][p][j] = 0.f;

    {
        const __half* Bbase = g_Wih_p + (size_t)ct * 4 * 96 * 64;
        #pragma unroll
        for (int r = 0; r < 12; r++) {
            int idx = tid + 256 * r;
            int kc = idx / 768;
            int e  = idx - kc * 768;
            int row = e >> 3, u = e & 7;
            cp16(sb + GX_OFF_B + kc * 12288 + SWZ(row * 128 + u * 16),
                 Bbase + (size_t)(kc * 96 + row) * 64 + u * 8);
        }
    }
    auto load_A = [&](int kc, int buf) {
        uint32_t base = sb + GX_OFF_A + buf * 32768;
        #pragma unroll
        for (int r = 0; r < 4; r++) {
            int idx = tid + 256 * r;
            int row = idx >> 3, u = idx & 7;
            size_t off = (size_t)(m0 + row) * 256 + kc * 64 + u * 8;
            uint32_t d = SWZ(row * 128 + u * 16);
            cp16(base + d, g_xhi + off);
            cp16(base + 16384 + d, g_xlo + off);
        }
        cp_commit();
    };

    load_A(0, 0);
    #pragma unroll 1
    for (int kc = 0; kc < 4; kc++) {
        if (kc + 1 < 4) { load_A(kc + 1, (kc + 1) & 1); cp_wait1(); }
        else            { cp_wait0(); }
        __syncthreads();

        uint32_t abufh = sb + GX_OFF_A + (kc & 1) * 32768;
        uint32_t abufl = abufh + 16384;
        uint32_t bbuf  = sb + GX_OFF_B + kc * 12288;

        #pragma unroll
        for (int ks = 0; ks < 4; ks++) {
            uint32_t af[2][4], al[2][4];
            #pragma unroll
            for (int mi = 0; mi < 2; mi++) {
                int row = mg * 32 + mi * 16 + (lane & 15);
                int colb = ks * 32 + ((lane >> 4) << 4);
                uint32_t d = SWZ(row * 128 + colb);
                ldm4(abufh + d, af[mi]);
                ldm4(abufl + d, al[mi]);
            }
            #pragma unroll
            for (int q = 0; q < 3; q++) {
                uint32_t bf[4];
                int n = sub * 48 + q * 16 + (lane & 7) + ((lane >> 4) << 3);
                int colb = ks * 32 + (((lane >> 3) & 1) << 4);
                ldm4(bbuf + SWZ(n * 128 + colb), bf);
                #pragma unroll
                for (int mi = 0; mi < 2; mi++) {
                    mma16816(acc[mi][2 * q + 0], af[mi], bf + 0);
                    mma16816(acc[mi][2 * q + 1], af[mi], bf + 2);
                    mma16816(acc[mi][2 * q + 0], al[mi], bf + 0);
                    mma16816(acc[mi][2 * q + 1], al[mi], bf + 2);
                }
            }
        }
        __syncthreads();
    }

    const int gid = lane >> 2, tid2 = lane & 3;
    #pragma unroll
    for (int mi = 0; mi < 2; mi++) {
        #pragma unroll
        for (int i = 0; i < 2; i++) {
            int m = m0 + mg * 32 + mi * 16 + gid + i * 8;
            #pragma unroll
            for (int q = 0; q < 3; q++) {
                #pragma unroll
                for (int cb = 0; cb < 2; cb++) {
                    #pragma unroll
                    for (int j = 0; j < 2; j++) {
                        int c = sub * 16 + cb * 8 + tid2 * 2 + j;
                        g_Gx[(size_t)m * 768 + ct * 96 + q * 32 + c] =
                            acc[mi][2 * q + cb][i * 2 + j] +
                            b_ih[q * 256 + ct * 32 + c];
                    }
                }
            }
        }
    }
}

// ---------------------------------------------------------------------------
// Fused 16-step recurrence — 14 warps: warp pair (rowgrp, half) shares 16
// H-rows, splits the 8 ct column tiles 4/4. One __syncthreads per t-step.
// W fragments prefetched one ks16 ahead in registers.
// ---------------------------------------------------------------------------
__global__ void __launch_bounds__(448, 1)
fused_rnn(const float* __restrict__ b_ih, const float* __restrict__ b_hh,
          float* __restrict__ fout)
{
    extern __shared__ char smem[];
    const int tid = threadIdx.x, wid = tid >> 5, lane = tid & 31;
    const int rowgrp = wid % 7;          // 7 row groups of 16 rows
    const int half   = wid / 7;          // 0: ct 0-3, 1: ct 4-7
    const int m0 = blockIdx.x * 112;
    const int mrow0 = rowgrp * 16;
    const uint32_t sb = smem_u32(smem);
    const int gid = lane >> 2, tid2 = lane & 3;

    // stage biases once
    float* sbias = (float*)(smem + FK_BIAS);
    for (int i = tid; i < 1536; i += 448)
        sbias[i] = (i < 768) ? b_ih[i] : b_hh[i - 768];
    __syncthreads();
    const float* sbi = sbias;
    const float* sbh = sbias + 768;

    #pragma unroll 1
    for (int t = 0; t < KW; t++) {
        const uint32_t curb = sb + ((t + 1) & 1) * FK_BUF;
        const uint32_t nxtb = sb + (t & 1) * FK_BUF;
        #pragma unroll 1
        for (int cti = 0; cti < 4; cti++) {
            const int ct = half * 4 + cti;
            float acc[12][4];
            #pragma unroll
            for (int nb = 0; nb < 12; nb++)
                #pragma unroll
                for (int j2 = 0; j2 < 4; j2++) acc[nb][j2] = 0.f;

            if (t > 0) {
                const uint4* __restrict__ wp =
                    &g_Wfrag[(size_t)ct * 16 * 6 * 32 + lane];
                // prime: ks16 = 0 fragments
                uint4 bv[6];
                #pragma unroll
                for (int p = 0; p < 6; p++) bv[p] = wp[p * 32];
                #pragma unroll
                for (int ks16 = 0; ks16 < 16; ks16++) {
                    uint32_t af[4];
                    {
                        int kc = ks16 >> 2, ks = ks16 & 3;
                        int row = mrow0 + (lane & 15);
                        int colb = ks * 32 + ((lane >> 4) << 4);
                        ldm4(curb + kc * FK_CHUNK + SWZ(row * 128 + colb), af);
                    }
                    uint4 nv[6];
                    if (ks16 < 15) {
                        #pragma unroll
                        for (int p = 0; p < 6; p++)
                            nv[p] = wp[((ks16 + 1) * 6 + p) * 32];
                    }
                    #pragma unroll
                    for (int p = 0; p < 6; p++) {
                        uint32_t bf0[2] = {bv[p].x, bv[p].y};
                        uint32_t bf1[2] = {bv[p].z, bv[p].w};
                        mma16816(acc[2 * p + 0], af, bf0);
                        mma16816(acc[2 * p + 1], af, bf1);
                    }
                    if (ks16 < 15) {
                        #pragma unroll
                        for (int p = 0; p < 6; p++) bv[p] = nv[p];
                    }
                }
            }

            // ---- epilogue: GRU gates, write h_next (fp16) to SMEM / out ----
            #pragma unroll
            for (int i = 0; i < 2; i++) {
                int rowl = mrow0 + gid + i * 8;          // 0..111
                int m = m0 + rowl;
                bool mval = m < MM;
                int l = m & 1023;
                bool valid = mval && (l - (KW - 1) + t >= 0);
                const float* gx = &g_Gx[(size_t)(m - (KW - 1) + t) * 768 + ct * 96];
                #pragma unroll
                for (int cb = 0; cb < 4; cb++) {
                    int c = cb * 8 + tid2 * 2;           // even, 0..30
                    int col = ct * 32 + c;
                    float2 gr, gz, gn;
                    if (valid) {
                        gr = *(const float2*)&gx[c];
                        gz = *(const float2*)&gx[32 + c];
                        gn = *(const float2*)&gx[64 + c];
                    } else {
                        gr = *(const float2*)&sbi[col];
                        gz = *(const float2*)&sbi[256 + col];
                        gn = *(const float2*)&sbi[512 + col];
                    }
                    float2 br = *(const float2*)&sbh[col];
                    float2 bz = *(const float2*)&sbh[256 + col];
                    float2 bn = *(const float2*)&sbh[512 + col];
                    float hp0 = 0.f, hp1 = 0.f;
                    if (t > 0) {
                        int kc2 = col >> 6, ch = col & 63;
                        uint32_t hv;
                        asm volatile("ld.shared.b32 %0, [%1];" : "=r"(hv)
                            : "r"(curb + kc2 * FK_CHUNK + SWZ(rowl * 128 + ch * 2)));
                        __half2 h2 = *(__half2*)&hv;
                        hp0 = __half2float(__low2half(h2));
                        hp1 = __half2float(__high2half(h2));
                    }
                    float r0 = sigm(gr.x + acc[cb][i * 2 + 0] + br.x);
                    float r1 = sigm(gr.y + acc[cb][i * 2 + 1] + br.y);
                    float z0 = sigm(gz.x + acc[4 + cb][i * 2 + 0] + bz.x);
                    float z1 = sigm(gz.y + acc[4 + cb][i * 2 + 1] + bz.y);
                    float n0 = ftanh(fmaf(r0, acc[8 + cb][i * 2 + 0] + bn.x, gn.x));
                    float n1 = ftanh(fmaf(r1, acc[8 + cb][i * 2 + 1] + bn.y, gn.y));
                    float h0 = fmaf(z0, hp0 - n0, n0);   // (1-z)n + z*hprev
                    float h1 = fmaf(z1, hp1 - n1, n1);
                    if (t == KW - 1) {
                        if (mval) {
                            float2 o = make_float2(h0, h1);
                            *(float2*)&fout[(size_t)m * 256 + col] = o;
                        }
                    } else {
                        __half2 h2 = __floats2half2_rn(h0, h1);
                        int kc2 = col >> 6, ch = col & 63;
                        uint32_t hv = *(uint32_t*)&h2;
                        asm volatile("st.shared.b32 [%0], %1;" ::
                            "r"(nxtb + kc2 * FK_CHUNK + SWZ(rowl * 128 + ch * 2)),
                            "r"(hv) : "memory");
                    }
                }
            }
        }
        // warp pair exchanges H columns across steps -> CTA barrier per t
        __syncthreads();
    }
}

// ---------------------------------------------------------------------------
extern "C" void kernel_launch(void* const* d_in, const int* in_sizes, int n_in,
                              void* d_out, int out_size)
{
    const float* x    = (const float*)d_in[0];
    const float* W_ih = (const float*)d_in[1];
    const float* W_hh = (const float*)d_in[2];
    const float* b_ih = (const float*)d_in[3];
    const float* b_hh = (const float*)d_in[4];
    float* out = (float*)d_out;

    cudaFuncSetAttribute(gx_gemm,
                         cudaFuncAttributeMaxDynamicSharedMemorySize, GX_SMEM);
    cudaFuncSetAttribute(fused_rnn,
                         cudaFuncAttributeMaxDynamicSharedMemorySize, FK_SMEM);

    pack_x_kernel<<<MM * 256 / 256, 256>>>(x);
    pack_wih_kernel<<<8 * 4 * 96 * 64 / 256, 256>>>(W_ih);
    pack_wfrag_kernel<<<8 * 16 * 6 * 32 / 256, 256>>>(W_hh);

    gx_gemm<<<dim3(8, MM / 128), 256, GX_SMEM>>>(b_ih);

    fused_rnn<<<147, 448, FK_SMEM>>>(b_ih, b_hh, out);
}

// round 10
// speedup vs baseline: 3.2955x; 1.6374x over previous
#include <cuda_runtime.h>
#include <cuda_fp16.h>
#include <cstdint>
#include <math.h>

#define MM 16384          // B*L
#define KW 16             // window

// ---------------------------------------------------------------------------
// Device scratch (allocation-free rule: device globals)
// ---------------------------------------------------------------------------
__device__ __half g_xhi[(size_t)MM * 256];
__device__ __half g_xlo[(size_t)MM * 256];
// Gx in lane-permuted layout: [m][ct*96 + q*32 + c'], c' = tid2*8 + (sub*2+cb)*2 + j
__device__ float  g_Gx[(size_t)MM * 768];
__device__ __half g_Wih_p[8 * 4 * 96 * 64];      // W_ih for Gx GEMM (ldmatrix layout)
__device__ uint4  g_Wfrag[8 * 16 * 6 * 32];      // W_hh in mma B-fragment order

#define SWZ(o) ((o) ^ (((o) >> 3) & 0x70))

// Gx GEMM smem
#define GX_OFF_B 0
#define GX_OFF_A 49152
#define GX_SMEM  114688

// fused kernel smem: H double buffer [buf][kc][row112][128B] + permuted biases
#define FK_CHUNK 14336           // 112 rows * 128 B
#define FK_BUF   57344           // 4 chunks
#define FK_BIAS  114688
#define FK_SMEM  (114688 + 6144)

// ---------------------------------------------------------------------------
// PTX helpers
// ---------------------------------------------------------------------------
__device__ __forceinline__ uint32_t smem_u32(const void* p) {
    uint32_t a;
    asm("{ .reg .u64 t; cvta.to.shared.u64 t, %1; cvt.u32.u64 %0, t; }"
        : "=r"(a) : "l"(p));
    return a;
}
__device__ __forceinline__ void cp16(uint32_t d, const void* s) {
    asm volatile("cp.async.cg.shared.global [%0], [%1], 16;"
                 :: "r"(d), "l"(s) : "memory");
}
__device__ __forceinline__ void cp_commit() { asm volatile("cp.async.commit_group;" ::: "memory"); }
__device__ __forceinline__ void cp_wait1()  { asm volatile("cp.async.wait_group 1;" ::: "memory"); }
__device__ __forceinline__ void cp_wait0()  { asm volatile("cp.async.wait_group 0;" ::: "memory"); }

__device__ __forceinline__ void ldm4(uint32_t a, uint32_t* r) {
    asm volatile("ldmatrix.sync.aligned.m8n8.x4.shared.b16 {%0,%1,%2,%3}, [%4];"
                 : "=r"(r[0]), "=r"(r[1]), "=r"(r[2]), "=r"(r[3]) : "r"(a));
}
__device__ __forceinline__ void mma16816(float* c, const uint32_t* a, const uint32_t* b) {
    asm volatile("mma.sync.aligned.m16n8k16.row.col.f32.f16.f16.f32 "
                 "{%0,%1,%2,%3}, {%4,%5,%6,%7}, {%8,%9}, {%0,%1,%2,%3};"
                 : "+f"(c[0]), "+f"(c[1]), "+f"(c[2]), "+f"(c[3])
                 : "r"(a[0]), "r"(a[1]), "r"(a[2]), "r"(a[3]), "r"(b[0]), "r"(b[1]));
}
__device__ __forceinline__ float tapp(float x) {
    float y;
    asm("tanh.approx.f32 %0, %1;" : "=f"(y) : "f"(x));
    return y;
}
__device__ __forceinline__ float sigm(float x)  { return fmaf(0.5f, tapp(0.5f * x), 0.5f); }

#define NBAR(id) asm volatile("bar.sync %0, 64;" :: "r"(id) : "memory")

// ---------------------------------------------------------------------------
// Prep kernels
// ---------------------------------------------------------------------------
__global__ void pack_x_kernel(const float* __restrict__ x) {
    size_t i = (size_t)blockIdx.x * 256 + threadIdx.x;
    float f = x[i];
    __half h = __float2half(f);
    g_xhi[i] = h;
    g_xlo[i] = __float2half(f - __half2float(h));
}

// W_ih ldmatrix layout: [ct][kc][row96][k64], row = sub*48 + g*16 + c
__global__ void pack_wih_kernel(const float* __restrict__ W_ih) {
    int idx = blockIdx.x * 256 + threadIdx.x;    // < 196608
    int k   = idx & 63;
    int r2  = idx >> 6;
    int row = r2 % 96;
    int r3  = r2 / 96;
    int kc  = r3 & 3;
    int ct  = r3 >> 2;
    int sub = row / 48;
    int rem = row % 48;
    int g = rem >> 4, c = rem & 15;
    g_Wih_p[idx] = __float2half(
        W_ih[(size_t)(g * 256 + ct * 32 + sub * 16 + c) * 256 + kc * 64 + k]);
}

// W_hh in mma.m16n8k16 B-fragment order
__global__ void pack_wfrag_kernel(const float* __restrict__ W_hh) {
    int idx = blockIdx.x * 256 + threadIdx.x;    // < 24576
    int lane = idx & 31;
    int r2 = idx >> 5;
    int p  = r2 % 6;
    int r3 = r2 / 6;
    int ks = r3 & 15;
    int ct = r3 >> 4;
    uint32_t u[4];
    #pragma unroll
    for (int r = 0; r < 4; r++) {
        int nb = p * 2 + (r >> 1);
        int q  = nb >> 2;
        int cc = (nb & 3) * 8 + (lane >> 2);
        int row = q * 256 + ct * 32 + cc;
        int k0  = ks * 16 + (r & 1) * 8 + (lane & 3) * 2;
        __half h0 = __float2half(W_hh[(size_t)row * 256 + k0]);
        __half h1 = __float2half(W_hh[(size_t)row * 256 + k0 + 1]);
        u[r] = (uint32_t)__half_as_ushort(h0) |
               ((uint32_t)__half_as_ushort(h1) << 16);
    }
    g_Wfrag[idx] = make_uint4(u[0], u[1], u[2], u[3]);
}

// ---------------------------------------------------------------------------
// Gx GEMM: Gx = x @ W_ih^T + b_ih, stored in lane-permuted order (STG.128)
// ---------------------------------------------------------------------------
__global__ void __launch_bounds__(256, 2)
gx_gemm(const float* __restrict__ b_ih)
{
    extern __shared__ char smem[];
    const int tid = threadIdx.x, wid = tid >> 5, lane = tid & 31;
    const int mg  = wid & 3;
    const int sub = wid >> 2;
    const int ct  = blockIdx.x;
    const int m0  = blockIdx.y * 128;
    const uint32_t sb = smem_u32(smem);

    float acc[2][6][4];
    #pragma unroll
    for (int mi = 0; mi < 2; mi++)
        #pragma unroll
        for (int p = 0; p < 6; p++)
            #pragma unroll
            for (int j = 0; j < 4; j++) acc[mi][p][j] = 0.f;

    {
        const __half* Bbase = g_Wih_p + (size_t)ct * 4 * 96 * 64;
        #pragma unroll
        for (int r = 0; r < 12; r++) {
            int idx = tid + 256 * r;
            int kc = idx / 768;
            int e  = idx - kc * 768;
            int row = e >> 3, u = e & 7;
            cp16(sb + GX_OFF_B + kc * 12288 + SWZ(row * 128 + u * 16),
                 Bbase + (size_t)(kc * 96 + row) * 64 + u * 8);
        }
    }
    auto load_A = [&](int kc, int buf) {
        uint32_t base = sb + GX_OFF_A + buf * 32768;
        #pragma unroll
        for (int r = 0; r < 4; r++) {
            int idx = tid + 256 * r;
            int row = idx >> 3, u = idx & 7;
            size_t off = (size_t)(m0 + row) * 256 + kc * 64 + u * 8;
            uint32_t d = SWZ(row * 128 + u * 16);
            cp16(base + d, g_xhi + off);
            cp16(base + 16384 + d, g_xlo + off);
        }
        cp_commit();
    };

    load_A(0, 0);
    #pragma unroll 1
    for (int kc = 0; kc < 4; kc++) {
        if (kc + 1 < 4) { load_A(kc + 1, (kc + 1) & 1); cp_wait1(); }
        else            { cp_wait0(); }
        __syncthreads();

        uint32_t abufh = sb + GX_OFF_A + (kc & 1) * 32768;
        uint32_t abufl = abufh + 16384;
        uint32_t bbuf  = sb + GX_OFF_B + kc * 12288;

        #pragma unroll
        for (int ks = 0; ks < 4; ks++) {
            uint32_t af[2][4], al[2][4];
            #pragma unroll
            for (int mi = 0; mi < 2; mi++) {
                int row = mg * 32 + mi * 16 + (lane & 15);
                int colb = ks * 32 + ((lane >> 4) << 4);
                uint32_t d = SWZ(row * 128 + colb);
                ldm4(abufh + d, af[mi]);
                ldm4(abufl + d, al[mi]);
            }
            #pragma unroll
            for (int q = 0; q < 3; q++) {
                uint32_t bf[4];
                int n = sub * 48 + q * 16 + (lane & 7) + ((lane >> 4) << 3);
                int colb = ks * 32 + (((lane >> 3) & 1) << 4);
                ldm4(bbuf + SWZ(n * 128 + colb), bf);
                #pragma unroll
                for (int mi = 0; mi < 2; mi++) {
                    mma16816(acc[mi][2 * q + 0], af[mi], bf + 0);
                    mma16816(acc[mi][2 * q + 1], af[mi], bf + 2);
                    mma16816(acc[mi][2 * q + 0], al[mi], bf + 0);
                    mma16816(acc[mi][2 * q + 1], al[mi], bf + 2);
                }
            }
        }
        __syncthreads();
    }

    // permuted epilogue: one STG.128 per (mi, i, q)
    const int gid = lane >> 2, tid2 = lane & 3;
    #pragma unroll
    for (int mi = 0; mi < 2; mi++) {
        #pragma unroll
        for (int i = 0; i < 2; i++) {
            int m = m0 + mg * 32 + mi * 16 + gid + i * 8;
            #pragma unroll
            for (int q = 0; q < 3; q++) {
                float4 v;
                v.x = acc[mi][2 * q + 0][i * 2 + 0] +
                      b_ih[q * 256 + ct * 32 + sub * 16 + 0 * 8 + tid2 * 2 + 0];
                v.y = acc[mi][2 * q + 0][i * 2 + 1] +
                      b_ih[q * 256 + ct * 32 + sub * 16 + 0 * 8 + tid2 * 2 + 1];
                v.z = acc[mi][2 * q + 1][i * 2 + 0] +
                      b_ih[q * 256 + ct * 32 + sub * 16 + 1 * 8 + tid2 * 2 + 0];
                v.w = acc[mi][2 * q + 1][i * 2 + 1] +
                      b_ih[q * 256 + ct * 32 + sub * 16 + 1 * 8 + tid2 * 2 + 1];
                *(float4*)&g_Gx[(size_t)m * 768 + ct * 96 + q * 32 +
                                tid2 * 8 + sub * 4] = v;
            }
        }
    }
}

// ---------------------------------------------------------------------------
// Fused 16-step recurrence — 14 warps (7 rowgrps x 2 ct-halves).
// Pair-local named barriers per t-step; A-ldmatrix and W-LDG both prefetched
// one ks16 ahead; Gx and biases in lane-permuted order (vector loads);
// activations via tanh.approx.
// ---------------------------------------------------------------------------
__global__ void __launch_bounds__(448, 1)
fused_rnn(const float* __restrict__ b_ih, const float* __restrict__ b_hh,
          float* __restrict__ fout)
{
    extern __shared__ char smem[];
    const int tid = threadIdx.x, wid = tid >> 5, lane = tid & 31;
    const int rowgrp = wid % 7;          // 7 row groups of 16 rows
    const int half   = wid / 7;          // 0: ct 0-3, 1: ct 4-7
    const int m0 = blockIdx.x * 112;
    const int mrow0 = rowgrp * 16;
    const uint32_t sb = smem_u32(smem);
    const int gid = lane >> 2, tid2 = lane & 3;

    // stage permuted biases once: [0..767] = b_ih', [768..1535] = b_hh'
    float* sbias = (float*)(smem + FK_BIAS);
    for (int i = tid; i < 1536; i += 448) {
        int ii = (i >= 768) ? (i - 768) : i;     // FIX: 768 is not a pow2 mask
        int bct = ii / 96, rem = ii % 96, q = rem >> 5, cp = rem & 31;
        int t2 = cp >> 3, e = cp & 7, cb = e >> 1, j = e & 1;
        int src = q * 256 + bct * 32 + cb * 8 + t2 * 2 + j;
        sbias[i] = (i < 768) ? b_ih[src] : b_hh[src];
    }
    __syncthreads();
    const float* sbi = sbias;
    const float* sbh = sbias + 768;

    #pragma unroll 1
    for (int t = 0; t < KW; t++) {
        const uint32_t curb = sb + ((t + 1) & 1) * FK_BUF;
        const uint32_t nxtb = sb + (t & 1) * FK_BUF;
        #pragma unroll 1
        for (int cti = 0; cti < 4; cti++) {
            const int ct = half * 4 + cti;
            float acc[12][4];
            #pragma unroll
            for (int nb = 0; nb < 12; nb++)
                #pragma unroll
                for (int j2 = 0; j2 < 4; j2++) acc[nb][j2] = 0.f;

            if (t > 0) {
                const uint4* __restrict__ wp =
                    &g_Wfrag[(size_t)ct * 16 * 6 * 32 + lane];
                uint4 bv[2][6];
                uint32_t af[2][4];
                #pragma unroll
                for (int p = 0; p < 6; p++) bv[0][p] = wp[p * 32];
                {
                    int row = mrow0 + (lane & 15);
                    int colb = ((lane >> 4) << 4);
                    ldm4(curb + SWZ(row * 128 + colb), af[0]);
                }
                #pragma unroll
                for (int ks16 = 0; ks16 < 16; ks16++) {
                    const int cur = ks16 & 1, nxt = cur ^ 1;
                    if (ks16 < 15) {
                        #pragma unroll
                        for (int p = 0; p < 6; p++)
                            bv[nxt][p] = wp[((ks16 + 1) * 6 + p) * 32];
                        int kc = (ks16 + 1) >> 2, ks = (ks16 + 1) & 3;
                        int row = mrow0 + (lane & 15);
                        int colb = ks * 32 + ((lane >> 4) << 4);
                        ldm4(curb + kc * FK_CHUNK + SWZ(row * 128 + colb), af[nxt]);
                    }
                    #pragma unroll
                    for (int p = 0; p < 6; p++) {
                        uint32_t bf0[2] = {bv[cur][p].x, bv[cur][p].y};
                        uint32_t bf1[2] = {bv[cur][p].z, bv[cur][p].w};
                        mma16816(acc[2 * p + 0], af[cur], bf0);
                        mma16816(acc[2 * p + 1], af[cur], bf1);
                    }
                }
            }

            // ---- epilogue ----
            #pragma unroll
            for (int i = 0; i < 2; i++) {
                int rowl = mrow0 + gid + i * 8;          // 0..111
                int m = m0 + rowl;
                bool mval = m < MM;
                int l = m & 1023;
                bool valid = mval && (l - (KW - 1) + t >= 0);

                float gv[3][8], bh[3][8];
                #pragma unroll
                for (int q = 0; q < 3; q++) {
                    float4 a0, a1, b0, b1;
                    if (valid) {
                        const float4* gp = (const float4*)
                            &g_Gx[(size_t)(m - (KW - 1) + t) * 768 +
                                  ct * 96 + q * 32 + tid2 * 8];
                        a0 = gp[0]; a1 = gp[1];
                    } else {
                        const float4* gp = (const float4*)
                            &sbi[ct * 96 + q * 32 + tid2 * 8];
                        a0 = gp[0]; a1 = gp[1];
                    }
                    const float4* bp = (const float4*)
                        &sbh[ct * 96 + q * 32 + tid2 * 8];
                    b0 = bp[0]; b1 = bp[1];
                    gv[q][0] = a0.x; gv[q][1] = a0.y; gv[q][2] = a0.z; gv[q][3] = a0.w;
                    gv[q][4] = a1.x; gv[q][5] = a1.y; gv[q][6] = a1.z; gv[q][7] = a1.w;
                    bh[q][0] = b0.x; bh[q][1] = b0.y; bh[q][2] = b0.z; bh[q][3] = b0.w;
                    bh[q][4] = b1.x; bh[q][5] = b1.y; bh[q][6] = b1.z; bh[q][7] = b1.w;
                }

                #pragma unroll
                for (int cb = 0; cb < 4; cb++) {
                    int col = ct * 32 + cb * 8 + tid2 * 2;
                    int kc2 = col >> 6, ch = col & 63;
                    float hp0 = 0.f, hp1 = 0.f;
                    if (t > 0) {
                        uint32_t hv;
                        asm volatile("ld.shared.b32 %0, [%1];" : "=r"(hv)
                            : "r"(curb + kc2 * FK_CHUNK + SWZ(rowl * 128 + ch * 2)));
                        __half2 h2 = *(__half2*)&hv;
                        hp0 = __half2float(__low2half(h2));
                        hp1 = __half2float(__high2half(h2));
                    }
                    int e0 = cb * 2, e1 = cb * 2 + 1;
                    float r0 = sigm(gv[0][e0] + acc[cb][i * 2 + 0] + bh[0][e0]);
                    float r1 = sigm(gv[0][e1] + acc[cb][i * 2 + 1] + bh[0][e1]);
                    float z0 = sigm(gv[1][e0] + acc[4 + cb][i * 2 + 0] + bh[1][e0]);
                    float z1 = sigm(gv[1][e1] + acc[4 + cb][i * 2 + 1] + bh[1][e1]);
                    float n0 = tapp(fmaf(r0, acc[8 + cb][i * 2 + 0] + bh[2][e0], gv[2][e0]));
                    float n1 = tapp(fmaf(r1, acc[8 + cb][i * 2 + 1] + bh[2][e1], gv[2][e1]));
                    float h0 = fmaf(z0, hp0 - n0, n0);   // (1-z)n + z*hprev
                    float h1 = fmaf(z1, hp1 - n1, n1);
                    if (t == KW - 1) {
                        if (mval) {
                            float2 o = make_float2(h0, h1);
                            *(float2*)&fout[(size_t)m * 256 + col] = o;
                        }
                    } else {
                        __half2 h2 = __floats2half2_rn(h0, h1);
                        uint32_t hv = *(uint32_t*)&h2;
                        asm volatile("st.shared.b32 [%0], %1;" ::
                            "r"(nxtb + kc2 * FK_CHUNK + SWZ(rowl * 128 + ch * 2)),
                            "r"(hv) : "memory");
                    }
                }
            }
        }
        // only the ct-half partner shares this warp's H columns: pair barrier
        if (t < KW - 1) NBAR(rowgrp + 1);
    }
}

// ---------------------------------------------------------------------------
extern "C" void kernel_launch(void* const* d_in, const int* in_sizes, int n_in,
                              void* d_out, int out_size)
{
    const float* x    = (const float*)d_in[0];
    const float* W_ih = (const float*)d_in[1];
    const float* W_hh = (const float*)d_in[2];
    const float* b_ih = (const float*)d_in[3];
    const float* b_hh = (const float*)d_in[4];
    float* out = (float*)d_out;

    cudaFuncSetAttribute(gx_gemm,
                         cudaFuncAttributeMaxDynamicSharedMemorySize, GX_SMEM);
    cudaFuncSetAttribute(fused_rnn,
                         cudaFuncAttributeMaxDynamicSharedMemorySize, FK_SMEM);

    pack_x_kernel<<<MM * 256 / 256, 256>>>(x);
    pack_wih_kernel<<<8 * 4 * 96 * 64 / 256, 256>>>(W_ih);
    pack_wfrag_kernel<<<8 * 16 * 6 * 32 / 256, 256>>>(W_hh);

    gx_gemm<<<dim3(8, MM / 128), 256, GX_SMEM>>>(b_ih);

    fused_rnn<<<147, 448, FK_SMEM>>>(b_ih, b_hh, out);
}